// round 1
// baseline (speedup 1.0000x reference)
#include <cuda_runtime.h>

#define N_TYPES 8
#define D 64
#define BM 128
#define E_MAX 1048576

// ---------------- scratch (__device__ globals; no allocation allowed) ----------
__device__ int g_counts[N_TYPES];
__device__ int g_offsets[N_TYPES + 1];
__device__ int g_cursor[N_TYPES];
__device__ int g_perm[E_MAX];
__device__ int g_is64;

// ---------------- helpers ------------------------------------------------------
__device__ __forceinline__ int get_type(const void* p, int i, int is64) {
    if (is64) return (int)((const long long*)p)[i];
    return ((const int*)p)[i];
}

__device__ __forceinline__ unsigned long long pack2(float f) {
    unsigned long long r;
    unsigned u = __float_as_uint(f);
    asm("mov.b64 %0, {%1, %1};" : "=l"(r) : "r"(u));
    return r;
}
__device__ __forceinline__ void ffma2(unsigned long long& c, unsigned long long a,
                                      unsigned long long b) {
    asm("fma.rn.f32x2 %0, %1, %2, %0;" : "+l"(c) : "l"(a), "l"(b));
}
__device__ __forceinline__ void unpack2(unsigned long long v, float& lo, float& hi) {
    unsigned a, b;
    asm("mov.b64 {%0, %1}, %2;" : "=r"(a), "=r"(b) : "l"(v));
    lo = __uint_as_float(a);
    hi = __uint_as_float(b);
}

// ---------------- dtype detection: int64 vs int32 edge_types -------------------
__global__ void k_detect(const int* __restrict__ t32, int E) {
    __shared__ int any;
    if (threadIdx.x == 0) any = 0;
    __syncthreads();
    int stride = E / 2048;
    if (stride < 1) stride = 1;
    for (int i = threadIdx.x; i < 1024; i += blockDim.x) {
        long long idx = 2LL * i * stride + 1;
        if (idx < E) {
            if (t32[idx] != 0) any = 1;
        }
    }
    __syncthreads();
    if (threadIdx.x == 0) g_is64 = any ? 0 : 1;
}

// ---------------- binning ------------------------------------------------------
__global__ void k_init() {
    if (threadIdx.x < N_TYPES) g_counts[threadIdx.x] = 0;
}

__global__ void k_hist(const void* __restrict__ types, int E) {
    __shared__ int s[N_TYPES];
    if (threadIdx.x < N_TYPES) s[threadIdx.x] = 0;
    __syncthreads();
    int is64 = g_is64;
    for (int i = blockIdx.x * blockDim.x + threadIdx.x; i < E;
         i += gridDim.x * blockDim.x) {
        atomicAdd(&s[get_type(types, i, is64)], 1);
    }
    __syncthreads();
    if (threadIdx.x < N_TYPES) atomicAdd(&g_counts[threadIdx.x], s[threadIdx.x]);
}

__global__ void k_prefix() {
    if (threadIdx.x == 0) {
        int acc = 0;
        for (int t = 0; t < N_TYPES; t++) {
            g_offsets[t] = acc;
            g_cursor[t] = acc;
            acc += g_counts[t];
        }
        g_offsets[N_TYPES] = acc;
    }
}

__global__ void k_scatter(const void* __restrict__ types, int E) {
    __shared__ int s_cnt[N_TYPES], s_base[N_TYPES];
    if (threadIdx.x < N_TYPES) s_cnt[threadIdx.x] = 0;
    __syncthreads();
    int e = blockIdx.x * blockDim.x + threadIdx.x;
    int t = 0, local = 0;
    int valid = (e < E);
    if (valid) {
        t = get_type(types, e, g_is64);
        local = atomicAdd(&s_cnt[t], 1);
    }
    __syncthreads();
    if (threadIdx.x < N_TYPES)
        s_base[threadIdx.x] = atomicAdd(&g_cursor[threadIdx.x], s_cnt[threadIdx.x]);
    __syncthreads();
    if (valid) g_perm[s_base[t] + local] = e;
}

// ---------------- grouped GEMM: BM=128, N=64, K=64, fp32 with f32x2 FMA --------
__global__ void __launch_bounds__(256) k_gemm(const float* __restrict__ X,
                                              const float* __restrict__ W,
                                              const float* __restrict__ Bv,
                                              float* __restrict__ out) {
    __shared__ float x_sT[D][BM];  // transposed X tile: [k][row], 32KB
    __shared__ float w_s[D][D];    // W[type]: [k][col], 16KB

    // ---- map blockIdx.x -> (type, tile_in_type) ----
    int tile = blockIdx.x;
    int type = -1, row_start = 0, m = 0;
    {
        int acc_tiles = 0;
        int off_prev = g_offsets[0];
#pragma unroll
        for (int t = 0; t < N_TYPES; t++) {
            int off_next = g_offsets[t + 1];
            int c = off_next - off_prev;
            int nt = (c + BM - 1) / BM;
            if (type < 0 && tile < acc_tiles + nt) {
                type = t;
                int lt = tile - acc_tiles;
                row_start = off_prev + lt * BM;
                m = off_next - row_start;
                if (m > BM) m = BM;
            }
            acc_tiles += nt;
            off_prev = off_next;
        }
    }
    if (type < 0) return;

    int tid = threadIdx.x;

    // ---- load W[type] into smem ----
    {
        const float4* Wt = reinterpret_cast<const float4*>(W + type * D * D);
        float4* ws = reinterpret_cast<float4*>(&w_s[0][0]);
#pragma unroll
        for (int i = 0; i < D * D / 4 / 256; i++) ws[tid + i * 256] = Wt[tid + i * 256];
    }

    // ---- gather X rows, store transposed ----
    // thread: row = tid & 127, half = tid >> 7 (each half loads 8 float4 = 32 k's)
    {
        int row_idx = tid & (BM - 1);
        int half = tid >> 7;
        int rr = row_idx < m ? row_idx : (m - 1);
        int e = g_perm[row_start + rr];
        const float4* Xe = reinterpret_cast<const float4*>(X + (size_t)e * D) + half * 8;
#pragma unroll
        for (int q = 0; q < 8; q++) {
            float4 v = Xe[q];
            int k0 = (half * 8 + q) * 4;
            x_sT[k0 + 0][row_idx] = v.x;
            x_sT[k0 + 1][row_idx] = v.y;
            x_sT[k0 + 2][row_idx] = v.z;
            x_sT[k0 + 3][row_idx] = v.w;
        }
    }
    __syncthreads();

    // ---- compute: thread -> 4 rows x 8 cols (16 f32x2 accumulators) ----
    int rg = tid >> 3;  // 0..31 -> rows rg*4 .. rg*4+3
    int cg = tid & 7;   // 0..7  -> cols cg*8 .. cg*8+7

    unsigned long long acc[4][4];
#pragma unroll
    for (int i = 0; i < 4; i++)
#pragma unroll
        for (int j = 0; j < 4; j++) acc[i][j] = 0ULL;

#pragma unroll 8
    for (int k = 0; k < D; k++) {
        float4 a4 = *reinterpret_cast<const float4*>(&x_sT[k][rg * 4]);
        const unsigned long long* bp =
            reinterpret_cast<const unsigned long long*>(&w_s[k][cg * 8]);
        unsigned long long b0 = bp[0], b1 = bp[1], b2 = bp[2], b3 = bp[3];
        unsigned long long a0 = pack2(a4.x), a1 = pack2(a4.y), a2 = pack2(a4.z),
                           a3 = pack2(a4.w);
        ffma2(acc[0][0], a0, b0); ffma2(acc[0][1], a0, b1);
        ffma2(acc[0][2], a0, b2); ffma2(acc[0][3], a0, b3);
        ffma2(acc[1][0], a1, b0); ffma2(acc[1][1], a1, b1);
        ffma2(acc[1][2], a1, b2); ffma2(acc[1][3], a1, b3);
        ffma2(acc[2][0], a2, b0); ffma2(acc[2][1], a2, b1);
        ffma2(acc[2][2], a2, b2); ffma2(acc[2][3], a2, b3);
        ffma2(acc[3][0], a3, b0); ffma2(acc[3][1], a3, b1);
        ffma2(acc[3][2], a3, b2); ffma2(acc[3][3], a3, b3);
    }

    // ---- epilogue: bias + relu + scattered store ----
    float bias[8];
    {
        const float* bp = Bv + type * D + cg * 8;
#pragma unroll
        for (int j = 0; j < 8; j++) bias[j] = bp[j];
    }

#pragma unroll
    for (int i = 0; i < 4; i++) {
        int ridx = rg * 4 + i;
        if (ridx < m) {
            int e = g_perm[row_start + ridx];
            float v[8];
#pragma unroll
            for (int j = 0; j < 4; j++) unpack2(acc[i][j], v[2 * j], v[2 * j + 1]);
#pragma unroll
            for (int j = 0; j < 8; j++) v[j] = fmaxf(v[j] + bias[j], 0.0f);
            float4* op = reinterpret_cast<float4*>(out + (size_t)e * D + cg * 8);
            op[0] = make_float4(v[0], v[1], v[2], v[3]);
            op[1] = make_float4(v[4], v[5], v[6], v[7]);
        }
    }
}

// ---------------- launch -------------------------------------------------------
extern "C" void kernel_launch(void* const* d_in, const int* in_sizes, int n_in,
                              void* d_out, int out_size) {
    const float* X = (const float*)d_in[0];
    const void* types = d_in[1];  // int64 or int32, detected on device
    const float* W = (const float*)d_in[2];
    const float* Bv = (const float*)d_in[3];
    float* out = (float*)d_out;
    int E = in_sizes[0] / D;  // edge_features is [E, 64]

    k_detect<<<1, 256>>>((const int*)types, E);
    k_init<<<1, 32>>>();
    k_hist<<<512, 256>>>(types, E);
    k_prefix<<<1, 32>>>();
    k_scatter<<<(E + 255) / 256, 256>>>(types, E);

    int max_tiles = (E + BM - 1) / BM + N_TYPES;  // padding worst case
    k_gemm<<<max_tiles, 256>>>(X, W, Bv, out);
}